// round 16
// baseline (speedup 1.0000x reference)
#include <cuda_runtime.h>
#include <cuda_bf16.h>
#include <cstdint>

#define BB 4
#define SS 1024
#define TT 2048
#define HID 1024
#define NH 16
#define NKV 4
#define HD 64
#define KVD (NKV*HD)   // 256

using bf16 = __nv_bfloat16;
using bf162 = __nv_bfloat162;

// ---------------- scratch (device globals; no runtime allocation) ------------
__device__ bf16 g_xh[BB*SS*HID],  g_xl[BB*SS*HID];
__device__ bf16 g_ch[BB*TT*HID],  g_cl[BB*TT*HID];
__device__ bf16 g_Wqh[HID*HID],   g_Wql[HID*HID];
__device__ bf16 g_Wkh[KVD*HID],   g_Wkl[KVD*HID];
__device__ bf16 g_Wvh[KVD*HID],   g_Wvl[KVD*HID];
__device__ bf16 g_Woh[HID*HID],   g_Wol[HID*HID];
__device__ bf16 g_Qh[BB*SS*HID],  g_Ql[BB*SS*HID];
__device__ bf16 g_Kh[BB*TT*KVD],  g_Kl[BB*TT*KVD];
__device__ bf16 g_Vh[BB*TT*KVD],  g_Vl[BB*TT*KVD];
__device__ bf16 g_Oh[BB*SS*HID],  g_Ol[BB*SS*HID];

// ---------------- helpers ----------------------------------------------------
__device__ __forceinline__ uint32_t s2u(const void* p){
    return (uint32_t)__cvta_generic_to_shared(p);
}
__device__ __forceinline__ void cpa16(uint32_t s, const void* g){
    asm volatile("cp.async.cg.shared.global [%0], [%1], 16;\n" :: "r"(s), "l"(g));
}
__device__ __forceinline__ void cp_commit(){ asm volatile("cp.async.commit_group;\n"); }
template<int N> __device__ __forceinline__ void cp_wait(){
    asm volatile("cp.async.wait_group %0;\n" :: "n"(N));
}
__device__ __forceinline__ void ldm4(uint32_t* r, uint32_t a){
    asm volatile("ldmatrix.sync.aligned.m8n8.x4.shared.b16 {%0,%1,%2,%3}, [%4];\n"
        : "=r"(r[0]),"=r"(r[1]),"=r"(r[2]),"=r"(r[3]) : "r"(a));
}
__device__ __forceinline__ void ldm4t(uint32_t* r, uint32_t a){
    asm volatile("ldmatrix.sync.aligned.m8n8.x4.trans.shared.b16 {%0,%1,%2,%3}, [%4];\n"
        : "=r"(r[0]),"=r"(r[1]),"=r"(r[2]),"=r"(r[3]) : "r"(a));
}
__device__ __forceinline__ void mma16816(float* c, const uint32_t* a, uint32_t b0, uint32_t b1){
    asm volatile("mma.sync.aligned.m16n8k16.row.col.f32.bf16.bf16.f32 "
        "{%0,%1,%2,%3}, {%4,%5,%6,%7}, {%8,%9}, {%0,%1,%2,%3};\n"
        : "+f"(c[0]),"+f"(c[1]),"+f"(c[2]),"+f"(c[3])
        : "r"(a[0]),"r"(a[1]),"r"(a[2]),"r"(a[3]), "r"(b0),"r"(b1));
}
__device__ __forceinline__ void split1(float x, bf16& h, bf16& l){
    h = __float2bfloat16(x);
    l = __float2bfloat16(x - __bfloat162float(h));
}

// ---------------- fused fp32 -> bf16 hi/lo split (6 segments, 1 launch) ------
struct SplitArgs {
    const float4* src[6];
    bf162* hi[6];
    bf162* lo[6];
    int cum[7];
};

__global__ void split_all_kernel(SplitArgs a){
    int blk = blockIdx.x;
    int s = 0;
#pragma unroll
    for (int k = 0; k < 6; k++) if (blk >= a.cum[k+1]) s = k+1;
    int i = (blk - a.cum[s])*256 + threadIdx.x;
    float4 f = a.src[s][i];
    bf16 h0,l0,h1,l1,h2,l2,h3,l3;
    split1(f.x,h0,l0); split1(f.y,h1,l1); split1(f.z,h2,l2); split1(f.w,h3,l3);
    bf162 H0; H0.x=h0; H0.y=h1;  bf162 H1; H1.x=h2; H1.y=h3;
    bf162 L0; L0.x=l0; L0.y=l1;  bf162 L1; L1.x=l2; L1.y=l3;
    a.hi[s][2*i] = H0; a.hi[s][2*i+1] = H1;
    a.lo[s][2*i] = L0; a.lo[s][2*i+1] = L1;
}

// ---------------- bf16x3 GEMM core, 128x128 tile, BK=32, 2-stage -------------
// Per-output-element accumulation order identical to validated kernel
// (ks asc, kk asc, streams hh,hl,lh) -> bit-identical C, canary preserved.
#define GEMM_SMEM 81920

template<bool SPLIT>
__device__ __forceinline__ void gemm_core(
    const bf16* __restrict__ Ah, const bf16* __restrict__ Al,
    const bf16* __restrict__ Bh, const bf16* __restrict__ Bl,
    float* __restrict__ Cf, bf16* __restrict__ Ch, bf16* __restrict__ Cl,
    int m0, int n0, int N, int K, float scale, bf16* smg)
{
    const int SA = 128*40;             // elems per array per stage
    const int STG = 4*SA;              // Ah,Al,Bh,Bl

    const int tid = threadIdx.x;
    const int lr = tid>>1, lcc = (tid&1)*2;     // loader: row, chunk pair
    const int warp = tid>>5, lane = tid&31;
    const int wm = (warp&3)*32, wn = (warp>>2)*64;
    const int arow = lane&15,                acol = (lane>>4)*8;
    const int brow = (lane&7)+(lane>>4)*8,   bcol = ((lane>>3)&1)*8;

    float acc[2][8][4];
#pragma unroll
    for (int mf=0;mf<2;mf++)
#pragma unroll
        for (int nf=0;nf<8;nf++)
#pragma unroll
            for (int q=0;q<4;q++) acc[mf][nf][q] = 0.f;

    const int NKs = K>>5;

    auto load_stage = [&](int ks, int st){
        bf16* s = smg + st*STG;
        const size_t k0 = (size_t)ks*32;
        const bf16* pAh = Ah + (size_t)(m0+lr)*K + k0;
        const bf16* pAl = Al + (size_t)(m0+lr)*K + k0;
        const bf16* pBh = Bh + (size_t)(n0+lr)*K + k0;
        const bf16* pBl = Bl + (size_t)(n0+lr)*K + k0;
#pragma unroll
        for (int i=0;i<2;i++){
            int c = (lcc+i)*8;
            cpa16(s2u(s +        lr*40 + c), pAh + c);
            cpa16(s2u(s + SA +   lr*40 + c), pAl + c);
            cpa16(s2u(s + 2*SA + lr*40 + c), pBh + c);
            cpa16(s2u(s + 3*SA + lr*40 + c), pBl + c);
        }
    };

    load_stage(0,0); cp_commit();
    for (int ks=0; ks<NKs; ks++){
        int st = ks&1;
        if (ks+1 < NKs){ load_stage(ks+1, st^1); cp_commit(); cp_wait<1>(); }
        else           { cp_wait<0>(); }
        __syncthreads();
        bf16* s = smg + st*STG;
#pragma unroll
        for (int kk=0; kk<32; kk+=16){
            uint32_t ah[2][4], al[2][4], bh[4][4], bl[4][4];
#pragma unroll
            for (int mf=0;mf<2;mf++){
                ldm4(ah[mf], s2u(s +      (wm+mf*16+arow)*40 + kk + acol));
                ldm4(al[mf], s2u(s + SA + (wm+mf*16+arow)*40 + kk + acol));
            }
#pragma unroll
            for (int nb=0;nb<4;nb++){
                ldm4(bh[nb], s2u(s + 2*SA + (wn+nb*16+brow)*40 + kk + bcol));
                ldm4(bl[nb], s2u(s + 3*SA + (wn+nb*16+brow)*40 + kk + bcol));
            }
#pragma unroll
            for (int mf=0;mf<2;mf++)
#pragma unroll
                for (int nf=0;nf<8;nf++){
                    uint32_t b0h=bh[nf>>1][(nf&1)*2], b1h=bh[nf>>1][(nf&1)*2+1];
                    uint32_t b0l=bl[nf>>1][(nf&1)*2], b1l=bl[nf>>1][(nf&1)*2+1];
                    mma16816(acc[mf][nf], ah[mf], b0h, b1h);
                    mma16816(acc[mf][nf], ah[mf], b0l, b1l);
                    mma16816(acc[mf][nf], al[mf], b0h, b1h);
                }
        }
        __syncthreads();
    }

#pragma unroll
    for (int mf=0;mf<2;mf++){
        int r0 = m0 + wm + mf*16 + (lane>>2);
#pragma unroll
        for (int nf=0;nf<8;nf++){
            int cc = n0 + wn + nf*8 + (lane&3)*2;
            float v00=acc[mf][nf][0]*scale, v01=acc[mf][nf][1]*scale;
            float v10=acc[mf][nf][2]*scale, v11=acc[mf][nf][3]*scale;
            if (SPLIT){
                bf16 h,l; bf162 H,L;
                split1(v00,h,l); H.x=h; L.x=l;
                split1(v01,h,l); H.y=h; L.y=l;
                *(bf162*)(Ch + (size_t)r0*N + cc) = H;
                *(bf162*)(Cl + (size_t)r0*N + cc) = L;
                split1(v10,h,l); H.x=h; L.x=l;
                split1(v11,h,l); H.y=h; L.y=l;
                *(bf162*)(Ch + (size_t)(r0+8)*N + cc) = H;
                *(bf162*)(Cl + (size_t)(r0+8)*N + cc) = L;
            } else {
                *(float2*)(Cf + (size_t)r0*N + cc)     = make_float2(v00,v01);
                *(float2*)(Cf + (size_t)(r0+8)*N + cc) = make_float2(v10,v11);
            }
        }
    }
}

// ---------------- Wo projection (fp32 out), 128x128 tile ---------------------
__global__ __launch_bounds__(256, 2)
void gemm_bf16x3(const bf16* __restrict__ Ah, const bf16* __restrict__ Al,
                 const bf16* __restrict__ Bh, const bf16* __restrict__ Bl,
                 float* __restrict__ Cf, int M, int N, int K)
{
    extern __shared__ bf16 smg[];
    gemm_core<false>(Ah, Al, Bh, Bl, Cf, nullptr, nullptr,
                     blockIdx.y*128, blockIdx.x*128, N, K, 1.0f, smg);
}

// ---------------- fused Q + K + V projection, one launch, 128x128 tiles ------
// blocks 0..255 : Q (n-tile = blk&7, m-tile = blk>>3)
// blocks 256..511: KV concat N=512 (n-tile = blk&3, m-tile = blk>>2)
__global__ __launch_bounds__(256, 2)
void gemm_qkv(const bf16* __restrict__ xh_, const bf16* __restrict__ xl_,
              const bf16* __restrict__ ch_, const bf16* __restrict__ cl_,
              const bf16* __restrict__ wqh_, const bf16* __restrict__ wql_,
              const bf16* __restrict__ wkh_, const bf16* __restrict__ wkl_,
              const bf16* __restrict__ wvh_, const bf16* __restrict__ wvl_,
              bf16* __restrict__ qh_, bf16* __restrict__ ql_,
              bf16* __restrict__ kh_, bf16* __restrict__ kl_,
              bf16* __restrict__ vh_, bf16* __restrict__ vl_)
{
    extern __shared__ bf16 smg[];
    int blk = blockIdx.x;
    if (blk < 256){
        int n0 = (blk & 7) * 128;
        int m0 = (blk >> 3) * 128;
        gemm_core<true>(xh_, xl_, wqh_, wql_, nullptr, qh_, ql_,
                        m0, n0, HID, HID, 0.125f, smg);
    } else {
        blk -= 256;
        int nfull = (blk & 3) * 128;
        int m0 = (blk >> 2) * 128;
        bool isV = nfull >= KVD;
        int n0 = isV ? nfull - KVD : nfull;
        gemm_core<true>(ch_, cl_,
                        isV ? wvh_ : wkh_, isV ? wvl_ : wkl_,
                        nullptr,
                        isV ? vh_ : kh_,  isV ? vl_ : kl_,
                        m0, n0, KVD, HID, 1.0f, smg);
    }
}

// ---------------- flash attention (FROZEN round-3/8 bytes) -------------------
#define ATTN_SMEM 91904
__global__ __launch_bounds__(256, 2)
void attn_mma(const bf16* __restrict__ Qh, const bf16* __restrict__ Ql,
              const bf16* __restrict__ Kh, const bf16* __restrict__ Kl,
              const bf16* __restrict__ Vh, const bf16* __restrict__ Vl,
              bf16* __restrict__ Oh, bf16* __restrict__ Ol)
{
    extern __shared__ unsigned char smraw[];
    bf16* sQh = (bf16*)smraw;           // [64][72]
    bf16* sQl = sQh + 64*72;
    bf16* sKh = sQl + 64*72;
    bf16* sKl = sKh + 64*72;
    bf16* sVh = sKl + 64*72;
    bf16* sVl = sVh + 64*72;
    bf16* sPh = sVl + 64*72;
    bf16* sPl = sPh + 64*72;
    float* sS   = (float*)(sPl + 64*72);  // [64][68]
    float* rowm = sS + 64*68;
    float* rowl = rowm + 64;
    float* rowsc= rowl + 64;

    const int tid = threadIdx.x, warp = tid>>5, lane = tid&31;
    const int s0 = blockIdx.x*64, h = blockIdx.y, b = blockIdx.z, g = h>>2;
    const int lr = tid>>3, lc = (tid&7)*8;
    const int wm = (warp&3)*16, wn = (warp>>2)*32;
    const int arow = lane&15,              acol = (lane>>4)*8;
    const int brow = (lane&7)+(lane>>4)*8, bcol = ((lane>>3)&1)*8;

    const bf16* Qgh = Qh + (size_t)(b*SS+s0)*HID + h*HD;
    const bf16* Qgl = Ql + (size_t)(b*SS+s0)*HID + h*HD;
#pragma unroll
    for (int p=0;p<2;p++){
        int rr = lr + p*32;
        cpa16(s2u(sQh + rr*72 + lc), Qgh + (size_t)rr*HID + lc);
        cpa16(s2u(sQl + rr*72 + lc), Qgl + (size_t)rr*HID + lc);
    }
    cp_commit();
    if (tid < 64){ rowm[tid] = -1e30f; rowl[tid] = 0.f; }

    float oacc[4][4];
#pragma unroll
    for (int nf=0;nf<4;nf++)
#pragma unroll
        for (int q=0;q<4;q++) oacc[nf][q] = 0.f;

    const bf16* Kgh = Kh + (size_t)b*TT*KVD + g*HD;
    const bf16* Kgl = Kl + (size_t)b*TT*KVD + g*HD;
    const bf16* Vgh = Vh + (size_t)b*TT*KVD + g*HD;
    const bf16* Vgl = Vl + (size_t)b*TT*KVD + g*HD;

    for (int kt=0; kt<TT; kt+=64){
#pragma unroll
        for (int p=0;p<2;p++){
            int rr = lr + p*32;
            const size_t go = (size_t)(kt+rr)*KVD + lc;
            cpa16(s2u(sKh + rr*72 + lc), Kgh + go);
            cpa16(s2u(sKl + rr*72 + lc), Kgl + go);
            cpa16(s2u(sVh + rr*72 + lc), Vgh + go);
            cpa16(s2u(sVl + rr*72 + lc), Vgl + go);
        }
        cp_commit(); cp_wait<0>();
        __syncthreads();

        float sc[4][4];
#pragma unroll
        for (int nf=0;nf<4;nf++)
#pragma unroll
            for (int q=0;q<4;q++) sc[nf][q] = 0.f;
#pragma unroll
        for (int kk=0; kk<64; kk+=16){
            uint32_t ah[4], al[4], bh[2][4], bl[2][4];
            ldm4(ah, s2u(sQh + (wm+arow)*72 + kk + acol));
            ldm4(al, s2u(sQl + (wm+arow)*72 + kk + acol));
#pragma unroll
            for (int nb=0;nb<2;nb++){
                ldm4(bh[nb], s2u(sKh + (wn+nb*16+brow)*72 + kk + bcol));
                ldm4(bl[nb], s2u(sKl + (wn+nb*16+brow)*72 + kk + bcol));
            }
#pragma unroll
            for (int nf=0;nf<4;nf++){
                uint32_t b0h=bh[nf>>1][(nf&1)*2], b1h=bh[nf>>1][(nf&1)*2+1];
                uint32_t b0l=bl[nf>>1][(nf&1)*2], b1l=bl[nf>>1][(nf&1)*2+1];
                mma16816(sc[nf], ah, b0h, b1h);
                mma16816(sc[nf], ah, b0l, b1l);
                mma16816(sc[nf], al, b0h, b1h);
            }
        }
        {
            int r0 = wm + (lane>>2);
#pragma unroll
            for (int nf=0;nf<4;nf++){
                int cc = wn + nf*8 + (lane&3)*2;
                *(float2*)(sS + r0*68 + cc)     = make_float2(sc[nf][0], sc[nf][1]);
                *(float2*)(sS + (r0+8)*68 + cc) = make_float2(sc[nf][2], sc[nf][3]);
            }
        }
        __syncthreads();

        {
            int i = tid>>2, sub = tid&3;
            float m_old = rowm[i];
            float m = m_old;
#pragma unroll
            for (int t=sub; t<64; t+=4) m = fmaxf(m, sS[i*68+t]);
            m = fmaxf(m, __shfl_xor_sync(0xffffffffu, m, 1));
            m = fmaxf(m, __shfl_xor_sync(0xffffffffu, m, 2));
            float sum = 0.f;
#pragma unroll
            for (int t=sub; t<64; t+=4){
                float p = __expf(sS[i*68+t] - m);
                bf16 ph = __float2bfloat16(p);
                sPh[i*72+t] = ph;
                sPl[i*72+t] = __float2bfloat16(p - __bfloat162float(ph));
                sum += p;
            }
            sum += __shfl_xor_sync(0xffffffffu, sum, 1);
            sum += __shfl_xor_sync(0xffffffffu, sum, 2);
            if (sub == 0){
                float scl = __expf(m_old - m);
                rowm[i] = m;
                rowl[i] = rowl[i]*scl + sum;
                rowsc[i] = scl;
            }
        }
        __syncthreads();

        {
            int r0 = wm + (lane>>2);
            float s0v = rowsc[r0], s1v = rowsc[r0+8];
#pragma unroll
            for (int nf=0;nf<4;nf++){
                oacc[nf][0]*=s0v; oacc[nf][1]*=s0v;
                oacc[nf][2]*=s1v; oacc[nf][3]*=s1v;
            }
        }
#pragma unroll
        for (int kk=0; kk<64; kk+=16){
            uint32_t ah[4], al[4], bh[2][4], bl[2][4];
            ldm4(ah, s2u(sPh + (wm+arow)*72 + kk + acol));
            ldm4(al, s2u(sPl + (wm+arow)*72 + kk + acol));
#pragma unroll
            for (int nb=0;nb<2;nb++){
                ldm4t(bh[nb], s2u(sVh + (kk+arow)*72 + wn + nb*16 + acol));
                ldm4t(bl[nb], s2u(sVl + (kk+arow)*72 + wn + nb*16 + acol));
            }
#pragma unroll
            for (int nf=0;nf<4;nf++){
                uint32_t b0h=bh[nf>>1][(nf&1)*2], b1h=bh[nf>>1][(nf&1)*2+1];
                uint32_t b0l=bl[nf>>1][(nf&1)*2], b1l=bl[nf>>1][(nf&1)*2+1];
                mma16816(oacc[nf], ah, b0h, b1h);
                mma16816(oacc[nf], ah, b0l, b1l);
                mma16816(oacc[nf], al, b0h, b1h);
            }
        }
        __syncthreads();
    }

    {
        int r0 = wm + (lane>>2);
        float inv0 = 1.f/rowl[r0], inv1 = 1.f/rowl[r0+8];
        size_t base = (size_t)(b*SS + s0)*HID + h*HD;
#pragma unroll
        for (int nf=0;nf<4;nf++){
            int cc = wn + nf*8 + (lane&3)*2;
            float v00=oacc[nf][0]*inv0, v01=oacc[nf][1]*inv0;
            float v10=oacc[nf][2]*inv1, v11=oacc[nf][3]*inv1;
            bf16 hh,ll; bf162 H,L;
            split1(v00,hh,ll); H.x=hh; L.x=ll;
            split1(v01,hh,ll); H.y=hh; L.y=ll;
            *(bf162*)(Oh + base + (size_t)r0*HID + cc) = H;
            *(bf162*)(Ol + base + (size_t)r0*HID + cc) = L;
            split1(v10,hh,ll); H.x=hh; L.x=ll;
            split1(v11,hh,ll); H.y=hh; L.y=ll;
            *(bf162*)(Oh + base + (size_t)(r0+8)*HID + cc) = H;
            *(bf162*)(Ol + base + (size_t)(r0+8)*HID + cc) = L;
        }
    }
}

// ---------------- launch ------------------------------------------------------
extern "C" void kernel_launch(void* const* d_in, const int* in_sizes, int n_in,
                              void* d_out, int out_size) {
    const float* x   = (const float*)d_in[0];
    const float* ctx = (const float*)d_in[1];
    const float* Wq  = (const float*)d_in[2];
    const float* Wk  = (const float*)d_in[3];
    const float* Wv  = (const float*)d_in[4];
    const float* Wo  = (const float*)d_in[5];
    float* out = (float*)d_out;

    void *xh,*xl,*ch,*cl,*wqh,*wql,*wkh,*wkl,*wvh,*wvl,*woh,*wol;
    void *qh,*ql,*kh,*kl,*vh,*vl,*oh,*ol;
    cudaGetSymbolAddress(&xh,g_xh);   cudaGetSymbolAddress(&xl,g_xl);
    cudaGetSymbolAddress(&ch,g_ch);   cudaGetSymbolAddress(&cl,g_cl);
    cudaGetSymbolAddress(&wqh,g_Wqh); cudaGetSymbolAddress(&wql,g_Wql);
    cudaGetSymbolAddress(&wkh,g_Wkh); cudaGetSymbolAddress(&wkl,g_Wkl);
    cudaGetSymbolAddress(&wvh,g_Wvh); cudaGetSymbolAddress(&wvl,g_Wvl);
    cudaGetSymbolAddress(&woh,g_Woh); cudaGetSymbolAddress(&wol,g_Wol);
    cudaGetSymbolAddress(&qh,g_Qh);   cudaGetSymbolAddress(&ql,g_Ql);
    cudaGetSymbolAddress(&kh,g_Kh);   cudaGetSymbolAddress(&kl,g_Kl);
    cudaGetSymbolAddress(&vh,g_Vh);   cudaGetSymbolAddress(&vl,g_Vl);
    cudaGetSymbolAddress(&oh,g_Oh);   cudaGetSymbolAddress(&ol,g_Ol);

    cudaFuncSetAttribute(gemm_bf16x3, cudaFuncAttributeMaxDynamicSharedMemorySize, GEMM_SMEM);
    cudaFuncSetAttribute(gemm_qkv,    cudaFuncAttributeMaxDynamicSharedMemorySize, GEMM_SMEM);
    cudaFuncSetAttribute(attn_mma,    cudaFuncAttributeMaxDynamicSharedMemorySize, ATTN_SMEM);

    // fused split (validated)
    SplitArgs sa;
    sa.src[0]=(const float4*)x;   sa.hi[0]=(bf162*)xh;  sa.lo[0]=(bf162*)xl;
    sa.src[1]=(const float4*)ctx; sa.hi[1]=(bf162*)ch;  sa.lo[1]=(bf162*)cl;
    sa.src[2]=(const float4*)Wq;  sa.hi[2]=(bf162*)wqh; sa.lo[2]=(bf162*)wql;
    sa.src[3]=(const float4*)Wk;  sa.hi[3]=(bf162*)wkh; sa.lo[3]=(bf162*)wkl;
    sa.src[4]=(const float4*)Wv;  sa.hi[4]=(bf162*)wvh; sa.lo[4]=(bf162*)wvl;
    sa.src[5]=(const float4*)Wo;  sa.hi[5]=(bf162*)woh; sa.lo[5]=(bf162*)wol;
    sa.cum[0]=0;     sa.cum[1]=4096;  sa.cum[2]=12288; sa.cum[3]=13312;
    sa.cum[4]=13568; sa.cum[5]=13824; sa.cum[6]=14848;
    split_all_kernel<<<14848, 256>>>(sa);

    // fused Q + K + V projections (one launch, 512 CTAs, 128x128 tiles)
    gemm_qkv<<<512, 256, GEMM_SMEM>>>(
        (const bf16*)xh,(const bf16*)xl,(const bf16*)ch,(const bf16*)cl,
        (const bf16*)wqh,(const bf16*)wql,
        (const bf16*)wkh,(const bf16*)wkl,
        (const bf16*)wvh,(const bf16*)wvl,
        (bf16*)qh,(bf16*)ql,(bf16*)kh,(bf16*)kl,(bf16*)vh,(bf16*)vl);

    // attention (frozen, validated)
    attn_mma<<<dim3(SS/64, NH, BB), 256, ATTN_SMEM>>>(
        (const bf16*)qh,(const bf16*)ql,(const bf16*)kh,(const bf16*)kl,
        (const bf16*)vh,(const bf16*)vl,(bf16*)oh,(bf16*)ol);

    // output projection -> fp32 out (256 CTAs, 128x128 tiles)
    gemm_bf16x3<<<dim3(HID/128, (BB*SS)/128), 256, GEMM_SMEM>>>(
        (const bf16*)oh,(const bf16*)ol,(const bf16*)woh,(const bf16*)wol,
        out, BB*SS, HID, HID);
}

// round 17
// speedup vs baseline: 1.0381x; 1.0381x over previous
#include <cuda_runtime.h>
#include <cuda_bf16.h>
#include <cstdint>

#define BB 4
#define SS 1024
#define TT 2048
#define HID 1024
#define NH 16
#define NKV 4
#define HD 64
#define KVD (NKV*HD)   // 256

using bf16 = __nv_bfloat16;
using bf162 = __nv_bfloat162;

// ---------------- scratch (device globals; no runtime allocation) ------------
__device__ bf16 g_xh[BB*SS*HID],  g_xl[BB*SS*HID];
__device__ bf16 g_ch[BB*TT*HID],  g_cl[BB*TT*HID];
__device__ bf16 g_Wqh[HID*HID],   g_Wql[HID*HID];
__device__ bf16 g_Wkh[KVD*HID],   g_Wkl[KVD*HID];
__device__ bf16 g_Wvh[KVD*HID],   g_Wvl[KVD*HID];
__device__ bf16 g_Woh[HID*HID],   g_Wol[HID*HID];
__device__ bf16 g_Qh[BB*SS*HID],  g_Ql[BB*SS*HID];
__device__ bf16 g_Kh[BB*TT*KVD],  g_Kl[BB*TT*KVD];
__device__ bf16 g_Vh[BB*TT*KVD],  g_Vl[BB*TT*KVD];
__device__ bf16 g_Oh[BB*SS*HID],  g_Ol[BB*SS*HID];

// ---------------- helpers ----------------------------------------------------
__device__ __forceinline__ uint32_t s2u(const void* p){
    return (uint32_t)__cvta_generic_to_shared(p);
}
__device__ __forceinline__ void cpa16(uint32_t s, const void* g){
    asm volatile("cp.async.cg.shared.global [%0], [%1], 16;\n" :: "r"(s), "l"(g));
}
__device__ __forceinline__ void cp_commit(){ asm volatile("cp.async.commit_group;\n"); }
template<int N> __device__ __forceinline__ void cp_wait(){
    asm volatile("cp.async.wait_group %0;\n" :: "n"(N));
}
__device__ __forceinline__ void ldm4(uint32_t* r, uint32_t a){
    asm volatile("ldmatrix.sync.aligned.m8n8.x4.shared.b16 {%0,%1,%2,%3}, [%4];\n"
        : "=r"(r[0]),"=r"(r[1]),"=r"(r[2]),"=r"(r[3]) : "r"(a));
}
__device__ __forceinline__ void ldm4t(uint32_t* r, uint32_t a){
    asm volatile("ldmatrix.sync.aligned.m8n8.x4.trans.shared.b16 {%0,%1,%2,%3}, [%4];\n"
        : "=r"(r[0]),"=r"(r[1]),"=r"(r[2]),"=r"(r[3]) : "r"(a));
}
__device__ __forceinline__ void mma16816(float* c, const uint32_t* a, uint32_t b0, uint32_t b1){
    asm volatile("mma.sync.aligned.m16n8k16.row.col.f32.bf16.bf16.f32 "
        "{%0,%1,%2,%3}, {%4,%5,%6,%7}, {%8,%9}, {%0,%1,%2,%3};\n"
        : "+f"(c[0]),"+f"(c[1]),"+f"(c[2]),"+f"(c[3])
        : "r"(a[0]),"r"(a[1]),"r"(a[2]),"r"(a[3]), "r"(b0),"r"(b1));
}
__device__ __forceinline__ void split1(float x, bf16& h, bf16& l){
    h = __float2bfloat16(x);
    l = __float2bfloat16(x - __bfloat162float(h));
}

// ---------------- fused fp32 -> bf16 hi/lo split (2 float4 / thread) ---------
struct SplitArgs {
    const float4* src[6];
    bf162* hi[6];
    bf162* lo[6];
    int cum[7];    // cumulative block counts; every segment n4 % 512 == 0
};

__global__ void split_all_kernel(SplitArgs a){
    int blk = blockIdx.x;
    int s = 0;
#pragma unroll
    for (int k = 0; k < 6; k++) if (blk >= a.cum[k+1]) s = k+1;
    int base = (blk - a.cum[s])*512 + threadIdx.x;
#pragma unroll
    for (int j = 0; j < 2; j++){
        int i = base + j*256;
        float4 f = a.src[s][i];
        bf16 h0,l0,h1,l1,h2,l2,h3,l3;
        split1(f.x,h0,l0); split1(f.y,h1,l1); split1(f.z,h2,l2); split1(f.w,h3,l3);
        bf162 H0; H0.x=h0; H0.y=h1;  bf162 H1; H1.x=h2; H1.y=h3;
        bf162 L0; L0.x=l0; L0.y=l1;  bf162 L1; L1.x=l2; L1.y=l3;
        a.hi[s][2*i] = H0; a.hi[s][2*i+1] = H1;
        a.lo[s][2*i] = L0; a.lo[s][2*i+1] = L1;
    }
}

// ---------------- bf16x3 GEMM core (BK=32, 2-stage, validated math) ----------
#define GEMM_SMEM 61440

template<bool SPLIT>
__device__ __forceinline__ void gemm_core(
    const bf16* __restrict__ Ah, const bf16* __restrict__ Al,
    const bf16* __restrict__ Bh, const bf16* __restrict__ Bl,
    float* __restrict__ Cf, bf16* __restrict__ Ch, bf16* __restrict__ Cl,
    int m0, int n0, int N, int K, float scale, bf16* smg)
{
    const int SA = 128*40, SB = 64*40;
    const int STG = 2*SA + 2*SB;

    const int tid = threadIdx.x;
    const int lr = tid>>2, lc = (tid&3)*8;
    const int warp = tid>>5, lane = tid&31;
    const int wm = (warp&3)*32, wn = (warp>>2)*32;
    const int arow = lane&15,                acol = (lane>>4)*8;
    const int brow = (lane&7)+(lane>>4)*8,   bcol = ((lane>>3)&1)*8;

    float acc[2][4][4];
#pragma unroll
    for (int mf=0;mf<2;mf++)
#pragma unroll
        for (int nf=0;nf<4;nf++)
#pragma unroll
            for (int q=0;q<4;q++) acc[mf][nf][q] = 0.f;

    const int NKs = K>>5;

    auto load_stage = [&](int ks, int st){
        bf16* s = smg + st*STG;
        const size_t k0 = (size_t)ks*32;
        const bf16* pAh = Ah + (size_t)(m0+lr)*K + k0 + lc;
        const bf16* pAl = Al + (size_t)(m0+lr)*K + k0 + lc;
        cpa16(s2u(s +        lr*40      + lc), pAh);
        cpa16(s2u(s +       (lr+64)*40  + lc), pAh + (size_t)64*K);
        cpa16(s2u(s + SA +   lr*40      + lc), pAl);
        cpa16(s2u(s + SA +  (lr+64)*40  + lc), pAl + (size_t)64*K);
        cpa16(s2u(s + 2*SA +      lr*40 + lc), Bh + (size_t)(n0+lr)*K + k0 + lc);
        cpa16(s2u(s + 2*SA + SB + lr*40 + lc), Bl + (size_t)(n0+lr)*K + k0 + lc);
    };

    load_stage(0,0); cp_commit();
    for (int ks=0; ks<NKs; ks++){
        int st = ks&1;
        if (ks+1 < NKs){ load_stage(ks+1, st^1); cp_commit(); cp_wait<1>(); }
        else           { cp_wait<0>(); }
        __syncthreads();
        bf16* s = smg + st*STG;
#pragma unroll
        for (int kk=0; kk<32; kk+=16){
            uint32_t ah[2][4], al[2][4], bh[2][4], bl[2][4];
#pragma unroll
            for (int mf=0;mf<2;mf++){
                ldm4(ah[mf], s2u(s +      (wm+mf*16+arow)*40 + kk + acol));
                ldm4(al[mf], s2u(s + SA + (wm+mf*16+arow)*40 + kk + acol));
            }
#pragma unroll
            for (int nb=0;nb<2;nb++){
                ldm4(bh[nb], s2u(s + 2*SA +      (wn+nb*16+brow)*40 + kk + bcol));
                ldm4(bl[nb], s2u(s + 2*SA + SB + (wn+nb*16+brow)*40 + kk + bcol));
            }
#pragma unroll
            for (int mf=0;mf<2;mf++)
#pragma unroll
                for (int nf=0;nf<4;nf++){
                    uint32_t b0h=bh[nf>>1][(nf&1)*2], b1h=bh[nf>>1][(nf&1)*2+1];
                    uint32_t b0l=bl[nf>>1][(nf&1)*2], b1l=bl[nf>>1][(nf&1)*2+1];
                    mma16816(acc[mf][nf], ah[mf], b0h, b1h);
                    mma16816(acc[mf][nf], ah[mf], b0l, b1l);
                    mma16816(acc[mf][nf], al[mf], b0h, b1h);
                }
        }
        __syncthreads();
    }

#pragma unroll
    for (int mf=0;mf<2;mf++){
        int r0 = m0 + wm + mf*16 + (lane>>2);
#pragma unroll
        for (int nf=0;nf<4;nf++){
            int cc = n0 + wn + nf*8 + (lane&3)*2;
            float v00=acc[mf][nf][0]*scale, v01=acc[mf][nf][1]*scale;
            float v10=acc[mf][nf][2]*scale, v11=acc[mf][nf][3]*scale;
            if (SPLIT){
                bf16 h,l; bf162 H,L;
                split1(v00,h,l); H.x=h; L.x=l;
                split1(v01,h,l); H.y=h; L.y=l;
                *(bf162*)(Ch + (size_t)r0*N + cc) = H;
                *(bf162*)(Cl + (size_t)r0*N + cc) = L;
                split1(v10,h,l); H.x=h; L.x=l;
                split1(v11,h,l); H.y=h; L.y=l;
                *(bf162*)(Ch + (size_t)(r0+8)*N + cc) = H;
                *(bf162*)(Cl + (size_t)(r0+8)*N + cc) = L;
            } else {
                *(float2*)(Cf + (size_t)r0*N + cc)     = make_float2(v00,v01);
                *(float2*)(Cf + (size_t)(r0+8)*N + cc) = make_float2(v10,v11);
            }
        }
    }
}

// ---------------- Wo projection (fp32 out), 3 CTAs/SM ------------------------
__global__ __launch_bounds__(256, 3)
void gemm_bf16x3(const bf16* __restrict__ Ah, const bf16* __restrict__ Al,
                 const bf16* __restrict__ Bh, const bf16* __restrict__ Bl,
                 float* __restrict__ Cf, int M, int N, int K)
{
    extern __shared__ bf16 smg[];
    gemm_core<false>(Ah, Al, Bh, Bl, Cf, nullptr, nullptr,
                     blockIdx.y*128, blockIdx.x*64, N, K, 1.0f, smg);
}

// ---------------- fused Q + K + V projection, one launch, 3 CTAs/SM ----------
__global__ __launch_bounds__(256, 3)
void gemm_qkv(const bf16* __restrict__ xh_, const bf16* __restrict__ xl_,
              const bf16* __restrict__ ch_, const bf16* __restrict__ cl_,
              const bf16* __restrict__ wqh_, const bf16* __restrict__ wql_,
              const bf16* __restrict__ wkh_, const bf16* __restrict__ wkl_,
              const bf16* __restrict__ wvh_, const bf16* __restrict__ wvl_,
              bf16* __restrict__ qh_, bf16* __restrict__ ql_,
              bf16* __restrict__ kh_, bf16* __restrict__ kl_,
              bf16* __restrict__ vh_, bf16* __restrict__ vl_)
{
    extern __shared__ bf16 smg[];
    int blk = blockIdx.x;
    if (blk < 512){
        int n0 = (blk & 15) * 64;
        int m0 = (blk >> 4) * 128;
        gemm_core<true>(xh_, xl_, wqh_, wql_, nullptr, qh_, ql_,
                        m0, n0, HID, HID, 0.125f, smg);
    } else {
        blk -= 512;
        int nfull = (blk & 7) * 64;
        int m0 = (blk >> 3) * 128;
        bool isV = nfull >= KVD;
        int n0 = isV ? nfull - KVD : nfull;
        gemm_core<true>(ch_, cl_,
                        isV ? wvh_ : wkh_, isV ? wvl_ : wkl_,
                        nullptr,
                        isV ? vh_ : kh_,  isV ? vl_ : kl_,
                        m0, n0, KVD, HID, 1.0f, smg);
    }
}

// ---------------- flash attention (FROZEN round-3/8 bytes) -------------------
#define ATTN_SMEM 91904
__global__ __launch_bounds__(256, 2)
void attn_mma(const bf16* __restrict__ Qh, const bf16* __restrict__ Ql,
              const bf16* __restrict__ Kh, const bf16* __restrict__ Kl,
              const bf16* __restrict__ Vh, const bf16* __restrict__ Vl,
              bf16* __restrict__ Oh, bf16* __restrict__ Ol)
{
    extern __shared__ unsigned char smraw[];
    bf16* sQh = (bf16*)smraw;           // [64][72]
    bf16* sQl = sQh + 64*72;
    bf16* sKh = sQl + 64*72;
    bf16* sKl = sKh + 64*72;
    bf16* sVh = sKl + 64*72;
    bf16* sVl = sVh + 64*72;
    bf16* sPh = sVl + 64*72;
    bf16* sPl = sPh + 64*72;
    float* sS   = (float*)(sPl + 64*72);  // [64][68]
    float* rowm = sS + 64*68;
    float* rowl = rowm + 64;
    float* rowsc= rowl + 64;

    const int tid = threadIdx.x, warp = tid>>5, lane = tid&31;
    const int s0 = blockIdx.x*64, h = blockIdx.y, b = blockIdx.z, g = h>>2;
    const int lr = tid>>3, lc = (tid&7)*8;
    const int wm = (warp&3)*16, wn = (warp>>2)*32;
    const int arow = lane&15,              acol = (lane>>4)*8;
    const int brow = (lane&7)+(lane>>4)*8, bcol = ((lane>>3)&1)*8;

    const bf16* Qgh = Qh + (size_t)(b*SS+s0)*HID + h*HD;
    const bf16* Qgl = Ql + (size_t)(b*SS+s0)*HID + h*HD;
#pragma unroll
    for (int p=0;p<2;p++){
        int rr = lr + p*32;
        cpa16(s2u(sQh + rr*72 + lc), Qgh + (size_t)rr*HID + lc);
        cpa16(s2u(sQl + rr*72 + lc), Qgl + (size_t)rr*HID + lc);
    }
    cp_commit();
    if (tid < 64){ rowm[tid] = -1e30f; rowl[tid] = 0.f; }

    float oacc[4][4];
#pragma unroll
    for (int nf=0;nf<4;nf++)
#pragma unroll
        for (int q=0;q<4;q++) oacc[nf][q] = 0.f;

    const bf16* Kgh = Kh + (size_t)b*TT*KVD + g*HD;
    const bf16* Kgl = Kl + (size_t)b*TT*KVD + g*HD;
    const bf16* Vgh = Vh + (size_t)b*TT*KVD + g*HD;
    const bf16* Vgl = Vl + (size_t)b*TT*KVD + g*HD;

    for (int kt=0; kt<TT; kt+=64){
#pragma unroll
        for (int p=0;p<2;p++){
            int rr = lr + p*32;
            const size_t go = (size_t)(kt+rr)*KVD + lc;
            cpa16(s2u(sKh + rr*72 + lc), Kgh + go);
            cpa16(s2u(sKl + rr*72 + lc), Kgl + go);
            cpa16(s2u(sVh + rr*72 + lc), Vgh + go);
            cpa16(s2u(sVl + rr*72 + lc), Vgl + go);
        }
        cp_commit(); cp_wait<0>();
        __syncthreads();

        float sc[4][4];
#pragma unroll
        for (int nf=0;nf<4;nf++)
#pragma unroll
            for (int q=0;q<4;q++) sc[nf][q] = 0.f;
#pragma unroll
        for (int kk=0; kk<64; kk+=16){
            uint32_t ah[4], al[4], bh[2][4], bl[2][4];
            ldm4(ah, s2u(sQh + (wm+arow)*72 + kk + acol));
            ldm4(al, s2u(sQl + (wm+arow)*72 + kk + acol));
#pragma unroll
            for (int nb=0;nb<2;nb++){
                ldm4(bh[nb], s2u(sKh + (wn+nb*16+brow)*72 + kk + bcol));
                ldm4(bl[nb], s2u(sKl + (wn+nb*16+brow)*72 + kk + bcol));
            }
#pragma unroll
            for (int nf=0;nf<4;nf++){
                uint32_t b0h=bh[nf>>1][(nf&1)*2], b1h=bh[nf>>1][(nf&1)*2+1];
                uint32_t b0l=bl[nf>>1][(nf&1)*2], b1l=bl[nf>>1][(nf&1)*2+1];
                mma16816(sc[nf], ah, b0h, b1h);
                mma16816(sc[nf], ah, b0l, b1l);
                mma16816(sc[nf], al, b0h, b1h);
            }
        }
        {
            int r0 = wm + (lane>>2);
#pragma unroll
            for (int nf=0;nf<4;nf++){
                int cc = wn + nf*8 + (lane&3)*2;
                *(float2*)(sS + r0*68 + cc)     = make_float2(sc[nf][0], sc[nf][1]);
                *(float2*)(sS + (r0+8)*68 + cc) = make_float2(sc[nf][2], sc[nf][3]);
            }
        }
        __syncthreads();

        {
            int i = tid>>2, sub = tid&3;
            float m_old = rowm[i];
            float m = m_old;
#pragma unroll
            for (int t=sub; t<64; t+=4) m = fmaxf(m, sS[i*68+t]);
            m = fmaxf(m, __shfl_xor_sync(0xffffffffu, m, 1));
            m = fmaxf(m, __shfl_xor_sync(0xffffffffu, m, 2));
            float sum = 0.f;
#pragma unroll
            for (int t=sub; t<64; t+=4){
                float p = __expf(sS[i*68+t] - m);
                bf16 ph = __float2bfloat16(p);
                sPh[i*72+t] = ph;
                sPl[i*72+t] = __float2bfloat16(p - __bfloat162float(ph));
                sum += p;
            }
            sum += __shfl_xor_sync(0xffffffffu, sum, 1);
            sum += __shfl_xor_sync(0xffffffffu, sum, 2);
            if (sub == 0){
                float scl = __expf(m_old - m);
                rowm[i] = m;
                rowl[i] = rowl[i]*scl + sum;
                rowsc[i] = scl;
            }
        }
        __syncthreads();

        {
            int r0 = wm + (lane>>2);
            float s0v = rowsc[r0], s1v = rowsc[r0+8];
#pragma unroll
            for (int nf=0;nf<4;nf++){
                oacc[nf][0]*=s0v; oacc[nf][1]*=s0v;
                oacc[nf][2]*=s1v; oacc[nf][3]*=s1v;
            }
        }
#pragma unroll
        for (int kk=0; kk<64; kk+=16){
            uint32_t ah[4], al[4], bh[2][4], bl[2][4];
            ldm4(ah, s2u(sPh + (wm+arow)*72 + kk + acol));
            ldm4(al, s2u(sPl + (wm+arow)*72 + kk + acol));
#pragma unroll
            for (int nb=0;nb<2;nb++){
                ldm4t(bh[nb], s2u(sVh + (kk+arow)*72 + wn + nb*16 + acol));
                ldm4t(bl[nb], s2u(sVl + (kk+arow)*72 + wn + nb*16 + acol));
            }
#pragma unroll
            for (int nf=0;nf<4;nf++){
                uint32_t b0h=bh[nf>>1][(nf&1)*2], b1h=bh[nf>>1][(nf&1)*2+1];
                uint32_t b0l=bl[nf>>1][(nf&1)*2], b1l=bl[nf>>1][(nf&1)*2+1];
                mma16816(oacc[nf], ah, b0h, b1h);
                mma16816(oacc[nf], ah, b0l, b1l);
                mma16816(oacc[nf], al, b0h, b1h);
            }
        }
        __syncthreads();
    }

    {
        int r0 = wm + (lane>>2);
        float inv0 = 1.f/rowl[r0], inv1 = 1.f/rowl[r0+8];
        size_t base = (size_t)(b*SS + s0)*HID + h*HD;
#pragma unroll
        for (int nf=0;nf<4;nf++){
            int cc = wn + nf*8 + (lane&3)*2;
            float v00=oacc[nf][0]*inv0, v01=oacc[nf][1]*inv0;
            float v10=oacc[nf][2]*inv1, v11=oacc[nf][3]*inv1;
            bf16 hh,ll; bf162 H,L;
            split1(v00,hh,ll); H.x=hh; L.x=ll;
            split1(v01,hh,ll); H.y=hh; L.y=ll;
            *(bf162*)(Oh + base + (size_t)r0*HID + cc) = H;
            *(bf162*)(Ol + base + (size_t)r0*HID + cc) = L;
            split1(v10,hh,ll); H.x=hh; L.x=ll;
            split1(v11,hh,ll); H.y=hh; L.y=ll;
            *(bf162*)(Oh + base + (size_t)(r0+8)*HID + cc) = H;
            *(bf162*)(Ol + base + (size_t)(r0+8)*HID + cc) = L;
        }
    }
}

// ---------------- launch ------------------------------------------------------
extern "C" void kernel_launch(void* const* d_in, const int* in_sizes, int n_in,
                              void* d_out, int out_size) {
    const float* x   = (const float*)d_in[0];
    const float* ctx = (const float*)d_in[1];
    const float* Wq  = (const float*)d_in[2];
    const float* Wk  = (const float*)d_in[3];
    const float* Wv  = (const float*)d_in[4];
    const float* Wo  = (const float*)d_in[5];
    float* out = (float*)d_out;

    void *xh,*xl,*ch,*cl,*wqh,*wql,*wkh,*wkl,*wvh,*wvl,*woh,*wol;
    void *qh,*ql,*kh,*kl,*vh,*vl,*oh,*ol;
    cudaGetSymbolAddress(&xh,g_xh);   cudaGetSymbolAddress(&xl,g_xl);
    cudaGetSymbolAddress(&ch,g_ch);   cudaGetSymbolAddress(&cl,g_cl);
    cudaGetSymbolAddress(&wqh,g_Wqh); cudaGetSymbolAddress(&wql,g_Wql);
    cudaGetSymbolAddress(&wkh,g_Wkh); cudaGetSymbolAddress(&wkl,g_Wkl);
    cudaGetSymbolAddress(&wvh,g_Wvh); cudaGetSymbolAddress(&wvl,g_Wvl);
    cudaGetSymbolAddress(&woh,g_Woh); cudaGetSymbolAddress(&wol,g_Wol);
    cudaGetSymbolAddress(&qh,g_Qh);   cudaGetSymbolAddress(&ql,g_Ql);
    cudaGetSymbolAddress(&kh,g_Kh);   cudaGetSymbolAddress(&kl,g_Kl);
    cudaGetSymbolAddress(&vh,g_Vh);   cudaGetSymbolAddress(&vl,g_Vl);
    cudaGetSymbolAddress(&oh,g_Oh);   cudaGetSymbolAddress(&ol,g_Ol);

    cudaFuncSetAttribute(gemm_bf16x3, cudaFuncAttributeMaxDynamicSharedMemorySize, GEMM_SMEM);
    cudaFuncSetAttribute(gemm_qkv,    cudaFuncAttributeMaxDynamicSharedMemorySize, GEMM_SMEM);
    cudaFuncSetAttribute(attn_mma,    cudaFuncAttributeMaxDynamicSharedMemorySize, ATTN_SMEM);

    // fused split: 512 float4 per block (2 per thread)
    // blocks per segment (n4/512): x 2048, ctx 4096, Wq 512, Wk 128, Wv 128, Wo 512
    SplitArgs sa;
    sa.src[0]=(const float4*)x;   sa.hi[0]=(bf162*)xh;  sa.lo[0]=(bf162*)xl;
    sa.src[1]=(const float4*)ctx; sa.hi[1]=(bf162*)ch;  sa.lo[1]=(bf162*)cl;
    sa.src[2]=(const float4*)Wq;  sa.hi[2]=(bf162*)wqh; sa.lo[2]=(bf162*)wql;
    sa.src[3]=(const float4*)Wk;  sa.hi[3]=(bf162*)wkh; sa.lo[3]=(bf162*)wkl;
    sa.src[4]=(const float4*)Wv;  sa.hi[4]=(bf162*)wvh; sa.lo[4]=(bf162*)wvl;
    sa.src[5]=(const float4*)Wo;  sa.hi[5]=(bf162*)woh; sa.lo[5]=(bf162*)wol;
    sa.cum[0]=0;    sa.cum[1]=2048; sa.cum[2]=6144; sa.cum[3]=6656;
    sa.cum[4]=6784; sa.cum[5]=6912; sa.cum[6]=7424;
    split_all_kernel<<<7424, 256>>>(sa);

    // fused Q + K + V projections (one launch, 1024 CTAs, 64-wide tiles)
    gemm_qkv<<<1024, 256, GEMM_SMEM>>>(
        (const bf16*)xh,(const bf16*)xl,(const bf16*)ch,(const bf16*)cl,
        (const bf16*)wqh,(const bf16*)wql,
        (const bf16*)wkh,(const bf16*)wkl,
        (const bf16*)wvh,(const bf16*)wvl,
        (bf16*)qh,(bf16*)ql,(bf16*)kh,(bf16*)kl,(bf16*)vh,(bf16*)vl);

    // attention (frozen, validated)
    attn_mma<<<dim3(SS/64, NH, BB), 256, ATTN_SMEM>>>(
        (const bf16*)qh,(const bf16*)ql,(const bf16*)kh,(const bf16*)kl,
        (const bf16*)vh,(const bf16*)vl,(bf16*)oh,(bf16*)ol);

    // output projection -> fp32 out
    gemm_bf16x3<<<dim3(HID/64, (BB*SS)/128), 256, GEMM_SMEM>>>(
        (const bf16*)oh,(const bf16*)ol,(const bf16*)woh,(const bf16*)wol,
        out, BB*SS, HID, HID);
}